// round 16
// baseline (speedup 1.0000x reference)
#include <cuda_runtime.h>
#include <cuda_bf16.h>
#include <math.h>
#include <stdint.h>

// Problem constants
#define BB 4
#define NN 2048
#define DD 512
#define HH 8
#define DK 64
#define FFN 2048
#define MROWS (BB*NN)          // 8192

// ---------------- scratch (device globals; allocation-free) ----------------
__device__ float g_xn [MROWS*DD];
__device__ float g_q  [MROWS*DD];            // fp32 (B,H,N,DK)
__device__ __nv_bfloat16 g_kb[MROWS*DD];     // bf16 (B,H,N,DK)
__device__ __nv_bfloat16 g_vb[MROWS*DD];     // bf16 (B,H,N,DK)
__device__ float g_att[MROWS*DD];            // (B,N,D)
__device__ float g_x2 [MROWS*DD];
__device__ float g_h  [MROWS*DD];
__device__ float g_act[MROWS*FFN];
__device__ unsigned short g_idx[(size_t)MROWS*NN];
__device__ int    g_cnt[MROWS];
__device__ int    g_maskmode;
__device__ double g_invf[32];

// ---------------- mask dtype probe -----------------------------------------
__global__ void probe_mask_kernel(const unsigned char* __restrict__ m) {
    __shared__ int ok;
    if (threadIdx.x == 0) ok = 1;
    __syncthreads();
    int bad = 0;
    for (int i = threadIdx.x; i < NN; i += blockDim.x)
        if (m[(size_t)i * (NN + 1)] == 0) bad = 1;
    if (bad) atomicAnd(&ok, 0);
    __syncthreads();
    if (threadIdx.x == 0) g_maskmode = ok ? 0 : 1;
}

// ---------------- build compact index lists (1 warp per query row) ---------
__global__ __launch_bounds__(256) void build_idx_kernel(const unsigned char* __restrict__ mask) {
    int warp = threadIdx.x >> 5;
    int lane = threadIdx.x & 31;
    int row = blockIdx.x * 8 + warp;
    if (row >= MROWS) return;
    int mode = g_maskmode;
    const unsigned char* m8 = mask + (size_t)row * NN;
    const unsigned int* m32 = ((const unsigned int*)mask) + (size_t)row * NN;
    unsigned short* dst = g_idx + (size_t)row * NN;
    int cnt = 0;
    for (int j0 = 0; j0 < NN; j0 += 32) {
        int on = mode == 0 ? (m8[j0 + lane] != 0) : (m32[j0 + lane] != 0u);
        unsigned bal = __ballot_sync(0xffffffffu, on);
        int pre = __popc(bal & ((1u << lane) - 1u));
        if (on) dst[cnt + pre] = (unsigned short)(j0 + lane);
        cnt += __popc(bal);
    }
    if (lane == 0) g_cnt[row] = cnt;
}

// ---------------- RoPE frequency table -------------------------------------
__global__ void rope_init_kernel() {
    int i = threadIdx.x;
    if (i < 32)
        g_invf[i] = exp2(-((double)(2 * i) / 64.0) * 13.287712379549448);
}

// ---------------- LayerNorm -------------------------------------------------
__global__ __launch_bounds__(128) void ln_kernel(const float* __restrict__ x,
                                                 const float* __restrict__ g,
                                                 const float* __restrict__ b,
                                                 float* __restrict__ out) {
    int row = blockIdx.x;
    int t = threadIdx.x;
    const float4* xr = (const float4*)(x + (size_t)row * DD);
    float4 v = xr[t];
    float s  = v.x + v.y + v.z + v.w;
    float s2 = fmaf(v.x, v.x, fmaf(v.y, v.y, fmaf(v.z, v.z, v.w * v.w)));
    #pragma unroll
    for (int off = 16; off > 0; off >>= 1) {
        s  += __shfl_xor_sync(0xffffffffu, s,  off);
        s2 += __shfl_xor_sync(0xffffffffu, s2, off);
    }
    __shared__ float sh[8];
    int w = t >> 5;
    if ((t & 31) == 0) { sh[w] = s; sh[4 + w] = s2; }
    __syncthreads();
    float ts  = sh[0] + sh[1] + sh[2] + sh[3];
    float ts2 = sh[4] + sh[5] + sh[6] + sh[7];
    float mean = ts * (1.0f / DD);
    float var  = ts2 * (1.0f / DD) - mean * mean;
    float inv  = rsqrtf(var + 1e-5f);
    float4 gv = ((const float4*)g)[t];
    float4 bv = ((const float4*)b)[t];
    float4 o;
    o.x = (v.x - mean) * inv * gv.x + bv.x;
    o.y = (v.y - mean) * inv * gv.y + bv.y;
    o.z = (v.z - mean) * inv * gv.z + bv.z;
    o.w = (v.w - mean) * inv * gv.w + bv.w;
    ((float4*)(out + (size_t)row * DD))[t] = o;
}

// ---------------- helpers ---------------------------------------------------
__device__ __forceinline__ void mma_tf32(float* d, const uint32_t* a, const uint32_t* b) {
    asm volatile("mma.sync.aligned.m16n8k8.row.col.f32.tf32.tf32.f32 "
                 "{%0,%1,%2,%3}, {%4,%5,%6,%7}, {%8,%9}, {%0,%1,%2,%3};"
                 : "+f"(d[0]), "+f"(d[1]), "+f"(d[2]), "+f"(d[3])
                 : "r"(a[0]), "r"(a[1]), "r"(a[2]), "r"(a[3]),
                   "r"(b[0]), "r"(b[1]));
}
__device__ __forceinline__ uint32_t smem_u32(const void* p) {
    uint32_t a;
    asm("{ .reg .u64 t; cvta.to.shared.u64 t, %1; cvt.u32.u64 %0, t; }" : "=r"(a) : "l"(p));
    return a;
}
__device__ __forceinline__ void cp16(uint32_t dst, const void* src) {
    asm volatile("cp.async.cg.shared.global [%0], [%1], 16;" :: "r"(dst), "l"(src) : "memory");
}

// ============ TF32 GEMM, cp.async 3-stage pipeline, raw-fp32-as-tf32 ========
#define GK_ASZ   10240                 // 128*80 bytes
#define GK_BSZ   8704                  // 16*544 bytes
#define GK_STAGE (GK_ASZ + GK_BSZ)     // 18944
#define GK_SMEM  (3 * GK_STAGE)        // 56832

template<int EPI, int OM>
__global__ __launch_bounds__(256, 2) void tgemm_kernel(const float* __restrict__ A,
                                                       const float* __restrict__ Bm,
                                                       const float* __restrict__ bias,
                                                       const float* __restrict__ res,
                                                       float* __restrict__ C,
                                                       __nv_bfloat16* __restrict__ Cb,
                                                       int M, int Nn, int K) {
    extern __shared__ char dsm[];
    uint32_t sb = smem_u32(dsm);
    int tid = threadIdx.x;
    int lane = tid & 31;
    int wid = tid >> 5;
    int wm = (wid & 3) * 32;
    int wn = (wid >> 2) * 64;
    int g = lane >> 2, t4 = lane & 3;
    int m0 = blockIdx.y * 128;
    int n0 = blockIdx.x * 128;

    int arow = tid >> 1;
    int aseg = (tid & 1) * 2;
    int brow = tid >> 4;
    int bseg = (tid & 15) * 2;
    const char* aSrc = (const char*)(A + (size_t)(m0 + arow) * K + aseg * 4);
    const char* bSrc = (const char*)(Bm + (size_t)brow * Nn + n0 + bseg * 4);
    uint32_t aDst = sb + (uint32_t)(arow * 80 + aseg * 16);
    uint32_t bDst = sb + GK_ASZ + (uint32_t)(brow * 544 + bseg * 16);
    size_t bAdv = (size_t)16 * Nn * 4;

    int NT = K >> 4;

    #pragma unroll
    for (int s = 0; s < 2; s++) {
        uint32_t off = (uint32_t)s * GK_STAGE;
        cp16(aDst + off,      aSrc + (size_t)s * 64);
        cp16(aDst + off + 16, aSrc + (size_t)s * 64 + 16);
        cp16(bDst + off,      bSrc + (size_t)s * bAdv);
        cp16(bDst + off + 16, bSrc + (size_t)s * bAdv + 16);
        asm volatile("cp.async.commit_group;" ::: "memory");
    }

    float acc[2][8][4];
    #pragma unroll
    for (int mt = 0; mt < 2; mt++)
        #pragma unroll
        for (int nt = 0; nt < 8; nt++)
            #pragma unroll
            for (int i = 0; i < 4; i++) acc[mt][nt][i] = 0.0f;

    for (int c = 0; c < NT; c++) {
        asm volatile("cp.async.wait_group 1;" ::: "memory");
        __syncthreads();
        int cn = c + 2;
        if (cn < NT) {
            uint32_t off = (uint32_t)(cn % 3) * GK_STAGE;
            cp16(aDst + off,      aSrc + (size_t)cn * 64);
            cp16(aDst + off + 16, aSrc + (size_t)cn * 64 + 16);
            cp16(bDst + off,      bSrc + (size_t)cn * bAdv);
            cp16(bDst + off + 16, bSrc + (size_t)cn * bAdv + 16);
        }
        asm volatile("cp.async.commit_group;" ::: "memory");

        const uint32_t* Asm = (const uint32_t*)(dsm + (c % 3) * GK_STAGE);
        const uint32_t* Bsm = (const uint32_t*)(dsm + (c % 3) * GK_STAGE + GK_ASZ);
        #pragma unroll
        for (int kk = 0; kk < 16; kk += 8) {
            uint32_t a[2][4];
            #pragma unroll
            for (int mt = 0; mt < 2; mt++) {
                int m = wm + mt * 16 + g;
                a[mt][0] = Asm[m * 20 + kk + t4];
                a[mt][1] = Asm[(m + 8) * 20 + kk + t4];
                a[mt][2] = Asm[m * 20 + kk + t4 + 4];
                a[mt][3] = Asm[(m + 8) * 20 + kk + t4 + 4];
            }
            uint32_t b[8][2];
            #pragma unroll
            for (int nt = 0; nt < 8; nt++) {
                int n = wn + nt * 8 + g;
                b[nt][0] = Bsm[(kk + t4) * 136 + n];
                b[nt][1] = Bsm[(kk + t4 + 4) * 136 + n];
            }
            #pragma unroll
            for (int mt = 0; mt < 2; mt++)
                #pragma unroll
                for (int nt = 0; nt < 8; nt++)
                    mma_tf32(acc[mt][nt], a[mt], b[nt]);
        }
    }

    #pragma unroll
    for (int mt = 0; mt < 2; mt++) {
        #pragma unroll
        for (int nt = 0; nt < 8; nt++) {
            int m = m0 + wm + mt * 16 + g;
            int n = n0 + wn + nt * 8 + 2 * t4;
            float bv0 = bias[n], bv1 = bias[n + 1];
            float v00 = acc[mt][nt][0] + bv0, v01 = acc[mt][nt][1] + bv1;
            float v10 = acc[mt][nt][2] + bv0, v11 = acc[mt][nt][3] + bv1;
            if (EPI == 1) {
                v00 = fmaxf(v00, 0.0f); v01 = fmaxf(v01, 0.0f);
                v10 = fmaxf(v10, 0.0f); v11 = fmaxf(v11, 0.0f);
            }
            if (EPI == 2) {
                float2 r0 = *(const float2*)(res + (size_t)m * Nn + n);
                float2 r1 = *(const float2*)(res + (size_t)(m + 8) * Nn + n);
                v00 += r0.x; v01 += r0.y; v10 += r1.x; v11 += r1.y;
            }
            if (OM == 0) {
                float2 p0; p0.x = v00; p0.y = v01;
                float2 p1; p1.x = v10; p1.y = v11;
                *(float2*)(C + (size_t)m * Nn + n) = p0;
                *(float2*)(C + (size_t)(m + 8) * Nn + n) = p1;
            } else {
                int h = n >> 6, d = n & 63;
                int b0_ = m >> 11, nn0 = m & (NN - 1);
                int b1_ = (m + 8) >> 11, nn1 = (m + 8) & (NN - 1);
                size_t o0 = (((size_t)(b0_ * HH + h) * NN + nn0) << 6) + d;
                size_t o1 = (((size_t)(b1_ * HH + h) * NN + nn1) << 6) + d;
                if (OM == 1) {
                    float2 p0; p0.x = v00; p0.y = v01;
                    float2 p1; p1.x = v10; p1.y = v11;
                    *(float2*)(C + o0) = p0;
                    *(float2*)(C + o1) = p1;
                } else {
                    __nv_bfloat162 p0, p1;
                    p0.x = __float2bfloat16(v00); p0.y = __float2bfloat16(v01);
                    p1.x = __float2bfloat16(v10); p1.y = __float2bfloat16(v11);
                    *(__nv_bfloat162*)&Cb[o0] = p0;
                    *(__nv_bfloat162*)&Cb[o1] = p1;
                }
            }
        }
    }
}

// ---------------- RoPE: q fp32, k bf16 -------------------------------------
__global__ __launch_bounds__(256) void rope_kernel(float* __restrict__ q,
                                                   __nv_bfloat16* __restrict__ k,
                                                   const int* __restrict__ positions) {
    int idx = blockIdx.x * blockDim.x + threadIdx.x;
    int pair = idx & 31;
    int r = idx >> 5;
    int n = r & (NN - 1);
    int bh = r >> 11;
    int b = bh >> 3;
    double pos = (double)positions[b * NN + n];
    double ang = pos * g_invf[pair];
    double kq  = rint(ang * 0.15915494309189535);
    float rr = (float)(ang - kq * 6.283185307179586);
    float c = __cosf(rr);
    float s = __sinf(rr);
    float* qp = q + (size_t)r * DK;
    __nv_bfloat16* kp = k + (size_t)r * DK;
    float q0 = qp[pair], q1 = qp[pair + 32];
    qp[pair]      = q0 * c - q1 * s;
    qp[pair + 32] = q1 * c + q0 * s;
    float k0 = __bfloat162float(kp[pair]);
    float k1 = __bfloat162float(kp[pair + 32]);
    kp[pair]      = __float2bfloat16(k0 * c - k1 * s);
    kp[pair + 32] = __float2bfloat16(k1 * c + k0 * s);
}

// ======== SMEM-tiled sparse attention: 64 query rows/block, 64-key tiles ====
// K/V streamed through SMEM (double-buffered cp.async); each quad walks its
// sorted index list within the tile window. L2 traffic drops ~13x vs gather.
#define AT3_TK 64
#define AT3_STRIDE 144                    // padded row stride (bank rotation)
#define AT3_TILEB (AT3_TK * AT3_STRIDE)   // 9216 bytes

__global__ __launch_bounds__(256) void attn_tile_kernel(const float* __restrict__ q,
                                                        const __nv_bfloat16* __restrict__ kb,
                                                        const __nv_bfloat16* __restrict__ vb,
                                                        float* __restrict__ out) {
    __shared__ char sK[2][AT3_TILEB];
    __shared__ char sV[2][AT3_TILEB];

    int bh = blockIdx.x;
    int b = bh >> 3, h = bh & 7;
    int tid = threadIdx.x;
    int ql = tid & 3;
    int row = blockIdx.y * 64 + (tid >> 2);
    int r = b * NN + row;
    unsigned qmask = 0xFu << ((tid & 31) & ~3);

    const unsigned short* list = g_idx + (size_t)r * NN;
    int n = g_cnt[r];

    const float* qr = q + ((size_t)bh * NN + row) * DK + ql * 16;
    float qreg[16];
    #pragma unroll
    for (int d = 0; d < 16; d += 4) {
        float4 t = *(const float4*)(qr + d);
        qreg[d] = t.x * 0.125f; qreg[d + 1] = t.y * 0.125f;
        qreg[d + 2] = t.z * 0.125f; qreg[d + 3] = t.w * 0.125f;
    }
    const char* kplane = (const char*)(kb + (size_t)bh * NN * DK);
    const char* vplane = (const char*)(vb + (size_t)bh * NN * DK);

    // loader mapping: 512 16B segs per 8KB tile; 2 per thread
    int sid0 = tid * 2;
    int lr0 = sid0 >> 3, ls0 = (sid0 & 7) * 16;
    int lr1 = (sid0 + 1) >> 3, ls1 = ((sid0 + 1) & 7) * 16;
    uint32_t k0d = smem_u32(&sK[0][0]) + (uint32_t)(lr0 * AT3_STRIDE + ls0);
    uint32_t k1d = smem_u32(&sK[0][0]) + (uint32_t)(lr1 * AT3_STRIDE + ls1);
    uint32_t v0d = smem_u32(&sV[0][0]) + (uint32_t)(lr0 * AT3_STRIDE + ls0);
    uint32_t v1d = smem_u32(&sV[0][0]) + (uint32_t)(lr1 * AT3_STRIDE + ls1);
    int so0 = lr0 * 128 + ls0;
    int so1 = lr1 * 128 + ls1;

    float o[16];
    #pragma unroll
    for (int d = 0; d < 16; d++) o[d] = 0.0f;
    float m = -INFINITY, l = 0.0f;

    // prologue: load tile 0 into buffer 0
    cp16(k0d, kplane + so0); cp16(k1d, kplane + so1);
    cp16(v0d, vplane + so0); cp16(v1d, vplane + so1);
    asm volatile("cp.async.commit_group;" ::: "memory");

    int p = 0;
    const int NTILE = NN / AT3_TK;     // 32
    for (int t = 0; t < NTILE; t++) {
        asm volatile("cp.async.wait_group 0;" ::: "memory");
        __syncthreads();               // tile t ready; prev processing done
        if (t + 1 < NTILE) {           // prefetch tile t+1 into buf^1
            uint32_t boff = (uint32_t)(((t + 1) & 1) * AT3_TILEB);
            size_t goff = (size_t)(t + 1) * AT3_TK * 128;
            cp16(k0d + boff, kplane + goff + so0);
            cp16(k1d + boff, kplane + goff + so1);
            cp16(v0d + boff, vplane + goff + so0);
            cp16(v1d + boff, vplane + goff + so1);
            asm volatile("cp.async.commit_group;" ::: "memory");
        }
        const char* Kt = sK[t & 1];
        const char* Vt = sV[t & 1];
        int hi = (t + 1) * AT3_TK;
        int base = t * AT3_TK;
        while (p < n) {
            int j = list[p];
            if (j >= hi) break;
            const char* kr = Kt + (j - base) * AT3_STRIDE + ql * 32;
            uint4 ku0 = *(const uint4*)(kr);
            uint4 ku1 = *(const uint4*)(kr + 16);
            float s0 = 0.f, s1 = 0.f;
            {
                float2 f;
                f = __bfloat1622float2(*(const __nv_bfloat162*)&ku0.x);
                s0 = fmaf(qreg[0], f.x, s0); s1 = fmaf(qreg[1], f.y, s1);
                f = __bfloat1622float2(*(const __nv_bfloat162*)&ku0.y);
                s0 = fmaf(qreg[2], f.x, s0); s1 = fmaf(qreg[3], f.y, s1);
                f = __bfloat1622float2(*(const __nv_bfloat162*)&ku0.z);
                s0 = fmaf(qreg[4], f.x, s0); s1 = fmaf(qreg[5], f.y, s1);
                f = __bfloat1622float2(*(const __nv_bfloat162*)&ku0.w);
                s0 = fmaf(qreg[6], f.x, s0); s1 = fmaf(qreg[7], f.y, s1);
                f = __bfloat1622float2(*(const __nv_bfloat162*)&ku1.x);
                s0 = fmaf(qreg[8], f.x, s0); s1 = fmaf(qreg[9], f.y, s1);
                f = __bfloat1622float2(*(const __nv_bfloat162*)&ku1.y);
                s0 = fmaf(qreg[10], f.x, s0); s1 = fmaf(qreg[11], f.y, s1);
                f = __bfloat1622float2(*(const __nv_bfloat162*)&ku1.z);
                s0 = fmaf(qreg[12], f.x, s0); s1 = fmaf(qreg[13], f.y, s1);
                f = __bfloat1622float2(*(const __nv_bfloat162*)&ku1.w);
                s0 = fmaf(qreg[14], f.x, s0); s1 = fmaf(qreg[15], f.y, s1);
            }
            const char* vr = Vt + (j - base) * AT3_STRIDE + ql * 32;
            uint4 vu0 = *(const uint4*)(vr);
            uint4 vu1 = *(const uint4*)(vr + 16);
            float s = s0 + s1;
            s += __shfl_xor_sync(qmask, s, 1);
            s += __shfl_xor_sync(qmask, s, 2);
            float newm = fmaxf(m, s);
            float alpha = __expf(m - newm);    // first key: exp(-inf)=0
            float pw = __expf(s - newm);
            l = l * alpha + pw;
            m = newm;
            {
                float2 f;
                f = __bfloat1622float2(*(const __nv_bfloat162*)&vu0.x);
                o[0] = fmaf(o[0], alpha, pw * f.x); o[1] = fmaf(o[1], alpha, pw * f.y);
                f = __bfloat1622float2(*(const __nv_bfloat162*)&vu0.y);
                o[2] = fmaf(o[2], alpha, pw * f.x); o[3] = fmaf(o[3], alpha, pw * f.y);
                f = __bfloat1622float2(*(const __nv_bfloat162*)&vu0.z);
                o[4] = fmaf(o[4], alpha, pw * f.x); o[5] = fmaf(o[5], alpha, pw * f.y);
                f = __bfloat1622float2(*(const __nv_bfloat162*)&vu0.w);
                o[6] = fmaf(o[6], alpha, pw * f.x); o[7] = fmaf(o[7], alpha, pw * f.y);
                f = __bfloat1622float2(*(const __nv_bfloat162*)&vu1.x);
                o[8] = fmaf(o[8], alpha, pw * f.x); o[9] = fmaf(o[9], alpha, pw * f.y);
                f = __bfloat1622float2(*(const __nv_bfloat162*)&vu1.y);
                o[10] = fmaf(o[10], alpha, pw * f.x); o[11] = fmaf(o[11], alpha, pw * f.y);
                f = __bfloat1622float2(*(const __nv_bfloat162*)&vu1.z);
                o[12] = fmaf(o[12], alpha, pw * f.x); o[13] = fmaf(o[13], alpha, pw * f.y);
                f = __bfloat1622float2(*(const __nv_bfloat162*)&vu1.w);
                o[14] = fmaf(o[14], alpha, pw * f.x); o[15] = fmaf(o[15], alpha, pw * f.y);
            }
            p++;
        }
        __syncthreads();               // all quads done with tile t buffers
    }

    float invl = 1.0f / l;             // diagonal => l > 0 always
    float* orow = out + ((size_t)b * NN + row) * DD + h * DK + ql * 16;
    #pragma unroll
    for (int d = 0; d < 16; d += 4) {
        float4 t;
        t.x = o[d] * invl;     t.y = o[d + 1] * invl;
        t.z = o[d + 2] * invl; t.w = o[d + 3] * invl;
        *(float4*)(orow + d) = t;
    }
}

// ---------------- host launcher --------------------------------------------
extern "C" void kernel_launch(void* const* d_in, const int* in_sizes, int n_in,
                              void* d_out, int out_size) {
    const float* x        = (const float*)d_in[0];
    const unsigned char* o2o = (const unsigned char*)d_in[1];
    const int*   positions= (const int*)d_in[2];
    const float* wq = (const float*)d_in[3];  const float* bq = (const float*)d_in[4];
    const float* wk = (const float*)d_in[5];  const float* bk = (const float*)d_in[6];
    const float* wv = (const float*)d_in[7];  const float* bv = (const float*)d_in[8];
    const float* wo = (const float*)d_in[9];  const float* bo = (const float*)d_in[10];
    const float* ln1_g = (const float*)d_in[11]; const float* ln1_b = (const float*)d_in[12];
    const float* ln2_g = (const float*)d_in[13]; const float* ln2_b = (const float*)d_in[14];
    const float* w1 = (const float*)d_in[15]; const float* b1 = (const float*)d_in[16];
    const float* w2 = (const float*)d_in[17]; const float* b2 = (const float*)d_in[18];
    float* out = (float*)d_out;

    float *p_xn, *p_q, *p_att, *p_x2, *p_h, *p_act;
    __nv_bfloat16 *p_kb, *p_vb;
    cudaGetSymbolAddress((void**)&p_xn,  g_xn);
    cudaGetSymbolAddress((void**)&p_q,   g_q);
    cudaGetSymbolAddress((void**)&p_kb,  g_kb);
    cudaGetSymbolAddress((void**)&p_vb,  g_vb);
    cudaGetSymbolAddress((void**)&p_att, g_att);
    cudaGetSymbolAddress((void**)&p_x2,  g_x2);
    cudaGetSymbolAddress((void**)&p_h,   g_h);
    cudaGetSymbolAddress((void**)&p_act, g_act);

    cudaFuncSetAttribute(tgemm_kernel<0,1>, cudaFuncAttributeMaxDynamicSharedMemorySize, GK_SMEM);
    cudaFuncSetAttribute(tgemm_kernel<0,2>, cudaFuncAttributeMaxDynamicSharedMemorySize, GK_SMEM);
    cudaFuncSetAttribute(tgemm_kernel<2,0>, cudaFuncAttributeMaxDynamicSharedMemorySize, GK_SMEM);
    cudaFuncSetAttribute(tgemm_kernel<1,0>, cudaFuncAttributeMaxDynamicSharedMemorySize, GK_SMEM);

    // 0) probes / tables / index lists
    probe_mask_kernel<<<1, 256>>>(o2o);
    rope_init_kernel<<<1, 32>>>();
    build_idx_kernel<<<MROWS / 8, 256>>>(o2o);

    // 1) LN1
    ln_kernel<<<MROWS, 128>>>(x, ln1_g, ln1_b, p_xn);

    // 2) Q/K/V projections -> (B,H,N,DK); Q fp32, K/V bf16
    dim3 gproj(DD / 128, MROWS / 128);
    tgemm_kernel<0,1><<<gproj, 256, GK_SMEM>>>(p_xn, wq, bq, nullptr, p_q, nullptr, MROWS, DD, DD);
    tgemm_kernel<0,2><<<gproj, 256, GK_SMEM>>>(p_xn, wk, bk, nullptr, nullptr, p_kb, MROWS, DD, DD);
    tgemm_kernel<0,2><<<gproj, 256, GK_SMEM>>>(p_xn, wv, bv, nullptr, nullptr, p_vb, MROWS, DD, DD);

    // 3) RoPE on q,k
    rope_kernel<<<(BB * HH * NN * 32) / 256, 256>>>(p_q, p_kb, positions);

    // 4) SMEM-tiled sparse attention -> (B,N,D)
    dim3 gatt(BB * HH, NN / 64);
    attn_tile_kernel<<<gatt, 256>>>(p_q, p_kb, p_vb, p_att);

    // 5) output projection + residual
    tgemm_kernel<2,0><<<gproj, 256, GK_SMEM>>>(p_att, wo, bo, x, p_x2, nullptr, MROWS, DD, DD);

    // 6) LN2
    ln_kernel<<<MROWS, 128>>>(p_x2, ln2_g, ln2_b, p_h);

    // 7) FFN up + relu
    dim3 gffn1(FFN / 128, MROWS / 128);
    tgemm_kernel<1,0><<<gffn1, 256, GK_SMEM>>>(p_h, w1, b1, nullptr, p_act, nullptr, MROWS, FFN, DD);

    // 8) FFN down + residual -> out
    tgemm_kernel<2,0><<<gproj, 256, GK_SMEM>>>(p_act, w2, b2, p_x2, out, nullptr, MROWS, DD, FFN);
}

// round 17
// speedup vs baseline: 1.0718x; 1.0718x over previous
#include <cuda_runtime.h>
#include <cuda_bf16.h>
#include <math.h>
#include <stdint.h>

// Problem constants
#define BB 4
#define NN 2048
#define DD 512
#define HH 8
#define DK 64
#define FFN 2048
#define MROWS (BB*NN)          // 8192

// ---------------- scratch (device globals; allocation-free) ----------------
__device__ float g_xn [MROWS*DD];
__device__ float g_q  [MROWS*DD];            // fp32 (B,H,N,DK)
__device__ __nv_bfloat16 g_kb[MROWS*DD];     // bf16 (B,H,N,DK)
__device__ __nv_bfloat16 g_vb[MROWS*DD];     // bf16 (B,H,N,DK)
__device__ float g_att[MROWS*DD];            // (B,N,D)
__device__ float g_x2 [MROWS*DD];
__device__ float g_h  [MROWS*DD];
__device__ float g_act[MROWS*FFN];
__device__ unsigned short g_idx[(size_t)MROWS*NN];
__device__ int    g_cnt[MROWS];
__device__ int    g_maskmode;
__device__ double g_invf[32];

// ---------------- mask dtype probe -----------------------------------------
__global__ void probe_mask_kernel(const unsigned char* __restrict__ m) {
    __shared__ int ok;
    if (threadIdx.x == 0) ok = 1;
    __syncthreads();
    int bad = 0;
    for (int i = threadIdx.x; i < NN; i += blockDim.x)
        if (m[(size_t)i * (NN + 1)] == 0) bad = 1;
    if (bad) atomicAnd(&ok, 0);
    __syncthreads();
    if (threadIdx.x == 0) g_maskmode = ok ? 0 : 1;
}

// ---------------- build compact index lists (1 warp per query row) ---------
__global__ __launch_bounds__(256) void build_idx_kernel(const unsigned char* __restrict__ mask) {
    int warp = threadIdx.x >> 5;
    int lane = threadIdx.x & 31;
    int row = blockIdx.x * 8 + warp;
    if (row >= MROWS) return;
    int mode = g_maskmode;
    const unsigned char* m8 = mask + (size_t)row * NN;
    const unsigned int* m32 = ((const unsigned int*)mask) + (size_t)row * NN;
    unsigned short* dst = g_idx + (size_t)row * NN;
    int cnt = 0;
    for (int j0 = 0; j0 < NN; j0 += 32) {
        int on = mode == 0 ? (m8[j0 + lane] != 0) : (m32[j0 + lane] != 0u);
        unsigned bal = __ballot_sync(0xffffffffu, on);
        int pre = __popc(bal & ((1u << lane) - 1u));
        if (on) dst[cnt + pre] = (unsigned short)(j0 + lane);
        cnt += __popc(bal);
    }
    if (lane == 0) g_cnt[row] = cnt;
}

// ---------------- RoPE frequency table -------------------------------------
__global__ void rope_init_kernel() {
    int i = threadIdx.x;
    if (i < 32)
        g_invf[i] = exp2(-((double)(2 * i) / 64.0) * 13.287712379549448);
}

// ---------------- LayerNorm -------------------------------------------------
__global__ __launch_bounds__(128) void ln_kernel(const float* __restrict__ x,
                                                 const float* __restrict__ g,
                                                 const float* __restrict__ b,
                                                 float* __restrict__ out) {
    int row = blockIdx.x;
    int t = threadIdx.x;
    const float4* xr = (const float4*)(x + (size_t)row * DD);
    float4 v = xr[t];
    float s  = v.x + v.y + v.z + v.w;
    float s2 = fmaf(v.x, v.x, fmaf(v.y, v.y, fmaf(v.z, v.z, v.w * v.w)));
    #pragma unroll
    for (int off = 16; off > 0; off >>= 1) {
        s  += __shfl_xor_sync(0xffffffffu, s,  off);
        s2 += __shfl_xor_sync(0xffffffffu, s2, off);
    }
    __shared__ float sh[8];
    int w = t >> 5;
    if ((t & 31) == 0) { sh[w] = s; sh[4 + w] = s2; }
    __syncthreads();
    float ts  = sh[0] + sh[1] + sh[2] + sh[3];
    float ts2 = sh[4] + sh[5] + sh[6] + sh[7];
    float mean = ts * (1.0f / DD);
    float var  = ts2 * (1.0f / DD) - mean * mean;
    float inv  = rsqrtf(var + 1e-5f);
    float4 gv = ((const float4*)g)[t];
    float4 bv = ((const float4*)b)[t];
    float4 o;
    o.x = (v.x - mean) * inv * gv.x + bv.x;
    o.y = (v.y - mean) * inv * gv.y + bv.y;
    o.z = (v.z - mean) * inv * gv.z + bv.z;
    o.w = (v.w - mean) * inv * gv.w + bv.w;
    ((float4*)(out + (size_t)row * DD))[t] = o;
}

// ---------------- helpers ---------------------------------------------------
__device__ __forceinline__ void mma_tf32(float* d, const uint32_t* a, const uint32_t* b) {
    asm volatile("mma.sync.aligned.m16n8k8.row.col.f32.tf32.tf32.f32 "
                 "{%0,%1,%2,%3}, {%4,%5,%6,%7}, {%8,%9}, {%0,%1,%2,%3};"
                 : "+f"(d[0]), "+f"(d[1]), "+f"(d[2]), "+f"(d[3])
                 : "r"(a[0]), "r"(a[1]), "r"(a[2]), "r"(a[3]),
                   "r"(b[0]), "r"(b[1]));
}
__device__ __forceinline__ uint32_t smem_u32(const void* p) {
    uint32_t a;
    asm("{ .reg .u64 t; cvta.to.shared.u64 t, %1; cvt.u32.u64 %0, t; }" : "=r"(a) : "l"(p));
    return a;
}
__device__ __forceinline__ void cp16(uint32_t dst, const void* src) {
    asm volatile("cp.async.cg.shared.global [%0], [%1], 16;" :: "r"(dst), "l"(src) : "memory");
}

// ============ TF32 GEMM, cp.async 3-stage pipeline, raw-fp32-as-tf32 ========
#define GK_ASZ   10240                 // 128*80 bytes
#define GK_BSZ   8704                  // 16*544 bytes
#define GK_STAGE (GK_ASZ + GK_BSZ)     // 18944
#define GK_SMEM  (3 * GK_STAGE)        // 56832

template<int EPI, int OM>
__global__ __launch_bounds__(256, 2) void tgemm_kernel(const float* __restrict__ A,
                                                       const float* __restrict__ Bm,
                                                       const float* __restrict__ bias,
                                                       const float* __restrict__ res,
                                                       float* __restrict__ C,
                                                       __nv_bfloat16* __restrict__ Cb,
                                                       int M, int Nn, int K) {
    extern __shared__ char dsm[];
    uint32_t sb = smem_u32(dsm);
    int tid = threadIdx.x;
    int lane = tid & 31;
    int wid = tid >> 5;
    int wm = (wid & 3) * 32;
    int wn = (wid >> 2) * 64;
    int g = lane >> 2, t4 = lane & 3;
    int m0 = blockIdx.y * 128;
    int n0 = blockIdx.x * 128;

    int arow = tid >> 1;
    int aseg = (tid & 1) * 2;
    int brow = tid >> 4;
    int bseg = (tid & 15) * 2;
    const char* aSrc = (const char*)(A + (size_t)(m0 + arow) * K + aseg * 4);
    const char* bSrc = (const char*)(Bm + (size_t)brow * Nn + n0 + bseg * 4);
    uint32_t aDst = sb + (uint32_t)(arow * 80 + aseg * 16);
    uint32_t bDst = sb + GK_ASZ + (uint32_t)(brow * 544 + bseg * 16);
    size_t bAdv = (size_t)16 * Nn * 4;

    int NT = K >> 4;

    #pragma unroll
    for (int s = 0; s < 2; s++) {
        uint32_t off = (uint32_t)s * GK_STAGE;
        cp16(aDst + off,      aSrc + (size_t)s * 64);
        cp16(aDst + off + 16, aSrc + (size_t)s * 64 + 16);
        cp16(bDst + off,      bSrc + (size_t)s * bAdv);
        cp16(bDst + off + 16, bSrc + (size_t)s * bAdv + 16);
        asm volatile("cp.async.commit_group;" ::: "memory");
    }

    float acc[2][8][4];
    #pragma unroll
    for (int mt = 0; mt < 2; mt++)
        #pragma unroll
        for (int nt = 0; nt < 8; nt++)
            #pragma unroll
            for (int i = 0; i < 4; i++) acc[mt][nt][i] = 0.0f;

    for (int c = 0; c < NT; c++) {
        asm volatile("cp.async.wait_group 1;" ::: "memory");
        __syncthreads();
        int cn = c + 2;
        if (cn < NT) {
            uint32_t off = (uint32_t)(cn % 3) * GK_STAGE;
            cp16(aDst + off,      aSrc + (size_t)cn * 64);
            cp16(aDst + off + 16, aSrc + (size_t)cn * 64 + 16);
            cp16(bDst + off,      bSrc + (size_t)cn * bAdv);
            cp16(bDst + off + 16, bSrc + (size_t)cn * bAdv + 16);
        }
        asm volatile("cp.async.commit_group;" ::: "memory");

        const uint32_t* Asm = (const uint32_t*)(dsm + (c % 3) * GK_STAGE);
        const uint32_t* Bsm = (const uint32_t*)(dsm + (c % 3) * GK_STAGE + GK_ASZ);
        #pragma unroll
        for (int kk = 0; kk < 16; kk += 8) {
            uint32_t a[2][4];
            #pragma unroll
            for (int mt = 0; mt < 2; mt++) {
                int m = wm + mt * 16 + g;
                a[mt][0] = Asm[m * 20 + kk + t4];
                a[mt][1] = Asm[(m + 8) * 20 + kk + t4];
                a[mt][2] = Asm[m * 20 + kk + t4 + 4];
                a[mt][3] = Asm[(m + 8) * 20 + kk + t4 + 4];
            }
            uint32_t b[8][2];
            #pragma unroll
            for (int nt = 0; nt < 8; nt++) {
                int n = wn + nt * 8 + g;
                b[nt][0] = Bsm[(kk + t4) * 136 + n];
                b[nt][1] = Bsm[(kk + t4 + 4) * 136 + n];
            }
            #pragma unroll
            for (int mt = 0; mt < 2; mt++)
                #pragma unroll
                for (int nt = 0; nt < 8; nt++)
                    mma_tf32(acc[mt][nt], a[mt], b[nt]);
        }
    }

    #pragma unroll
    for (int mt = 0; mt < 2; mt++) {
        #pragma unroll
        for (int nt = 0; nt < 8; nt++) {
            int m = m0 + wm + mt * 16 + g;
            int n = n0 + wn + nt * 8 + 2 * t4;
            float bv0 = bias[n], bv1 = bias[n + 1];
            float v00 = acc[mt][nt][0] + bv0, v01 = acc[mt][nt][1] + bv1;
            float v10 = acc[mt][nt][2] + bv0, v11 = acc[mt][nt][3] + bv1;
            if (EPI == 1) {
                v00 = fmaxf(v00, 0.0f); v01 = fmaxf(v01, 0.0f);
                v10 = fmaxf(v10, 0.0f); v11 = fmaxf(v11, 0.0f);
            }
            if (EPI == 2) {
                float2 r0 = *(const float2*)(res + (size_t)m * Nn + n);
                float2 r1 = *(const float2*)(res + (size_t)(m + 8) * Nn + n);
                v00 += r0.x; v01 += r0.y; v10 += r1.x; v11 += r1.y;
            }
            if (OM == 0) {
                float2 p0; p0.x = v00; p0.y = v01;
                float2 p1; p1.x = v10; p1.y = v11;
                *(float2*)(C + (size_t)m * Nn + n) = p0;
                *(float2*)(C + (size_t)(m + 8) * Nn + n) = p1;
            } else {
                int h = n >> 6, d = n & 63;
                int b0_ = m >> 11, nn0 = m & (NN - 1);
                int b1_ = (m + 8) >> 11, nn1 = (m + 8) & (NN - 1);
                size_t o0 = (((size_t)(b0_ * HH + h) * NN + nn0) << 6) + d;
                size_t o1 = (((size_t)(b1_ * HH + h) * NN + nn1) << 6) + d;
                if (OM == 1) {
                    float2 p0; p0.x = v00; p0.y = v01;
                    float2 p1; p1.x = v10; p1.y = v11;
                    *(float2*)(C + o0) = p0;
                    *(float2*)(C + o1) = p1;
                } else {
                    __nv_bfloat162 p0, p1;
                    p0.x = __float2bfloat16(v00); p0.y = __float2bfloat16(v01);
                    p1.x = __float2bfloat16(v10); p1.y = __float2bfloat16(v11);
                    *(__nv_bfloat162*)&Cb[o0] = p0;
                    *(__nv_bfloat162*)&Cb[o1] = p1;
                }
            }
        }
    }
}

// ---------------- RoPE: q fp32, k bf16 -------------------------------------
__global__ __launch_bounds__(256) void rope_kernel(float* __restrict__ q,
                                                   __nv_bfloat16* __restrict__ k,
                                                   const int* __restrict__ positions) {
    int idx = blockIdx.x * blockDim.x + threadIdx.x;
    int pair = idx & 31;
    int r = idx >> 5;
    int n = r & (NN - 1);
    int bh = r >> 11;
    int b = bh >> 3;
    double pos = (double)positions[b * NN + n];
    double ang = pos * g_invf[pair];
    double kq  = rint(ang * 0.15915494309189535);
    float rr = (float)(ang - kq * 6.283185307179586);
    float c = __cosf(rr);
    float s = __sinf(rr);
    float* qp = q + (size_t)r * DK;
    __nv_bfloat16* kp = k + (size_t)r * DK;
    float q0 = qp[pair], q1 = qp[pair + 32];
    qp[pair]      = q0 * c - q1 * s;
    qp[pair + 32] = q1 * c + q0 * s;
    float k0 = __bfloat162float(kp[pair]);
    float k1 = __bfloat162float(kp[pair + 32]);
    kp[pair]      = __float2bfloat16(k0 * c - k1 * s);
    kp[pair + 32] = __float2bfloat16(k1 * c + k0 * s);
}

// ====== windowed L1-reuse sparse attention: 4 threads per (b,h,row) =========
// 128 query rows per block (512 threads) walk sorted key lists in 16 windows
// of 128 keys. All quads in a block traverse the same 64KB K/V region
// concurrently -> L1 captures ~13x reuse. No barriers; ascending key order
// keeps numerics identical to the plain gather kernel.
#define AW_ROWS 128
#define AW_WIN  128
__global__ __launch_bounds__(512) void attn_win_kernel(const float* __restrict__ q,
                                                       const __nv_bfloat16* __restrict__ kb,
                                                       const __nv_bfloat16* __restrict__ vb,
                                                       float* __restrict__ out) {
    int bh = blockIdx.x;
    int b = bh >> 3, h = bh & 7;
    int tid = threadIdx.x;
    int ql = tid & 3;
    int row = blockIdx.y * AW_ROWS + (tid >> 2);
    int r = b * NN + row;
    unsigned qmask = 0xFu << ((tid & 31) & ~3);

    const unsigned short* list = g_idx + (size_t)r * NN;
    int n = g_cnt[r];

    const float* qr = q + ((size_t)bh * NN + row) * DK + ql * 16;
    float qreg[16];
    #pragma unroll
    for (int d = 0; d < 16; d += 4) {
        float4 t = *(const float4*)(qr + d);
        qreg[d] = t.x * 0.125f; qreg[d + 1] = t.y * 0.125f;
        qreg[d + 2] = t.z * 0.125f; qreg[d + 3] = t.w * 0.125f;
    }
    const __nv_bfloat16* kbase = kb + (size_t)bh * NN * DK + ql * 16;
    const __nv_bfloat16* vbase = vb + (size_t)bh * NN * DK + ql * 16;

    float o[16];
    #pragma unroll
    for (int d = 0; d < 16; d++) o[d] = 0.0f;
    float m = -INFINITY, l = 0.0f;

    int p = 0;
    #pragma unroll 1
    for (int w = 0; w < NN / AW_WIN; w++) {
        int hi = (w + 1) * AW_WIN;
        while (p < n) {
            int j = list[p];
            if (j >= hi) break;
            uint4 ku0 = *(const uint4*)(kbase + (size_t)j * DK);
            uint4 ku1 = *(const uint4*)(kbase + (size_t)j * DK + 8);
            uint4 vu0 = *(const uint4*)(vbase + (size_t)j * DK);
            uint4 vu1 = *(const uint4*)(vbase + (size_t)j * DK + 8);
            float s0 = 0.f, s1 = 0.f;
            {
                float2 f;
                f = __bfloat1622float2(*(const __nv_bfloat162*)&ku0.x);
                s0 = fmaf(qreg[0], f.x, s0); s1 = fmaf(qreg[1], f.y, s1);
                f = __bfloat1622float2(*(const __nv_bfloat162*)&ku0.y);
                s0 = fmaf(qreg[2], f.x, s0); s1 = fmaf(qreg[3], f.y, s1);
                f = __bfloat1622float2(*(const __nv_bfloat162*)&ku0.z);
                s0 = fmaf(qreg[4], f.x, s0); s1 = fmaf(qreg[5], f.y, s1);
                f = __bfloat1622float2(*(const __nv_bfloat162*)&ku0.w);
                s0 = fmaf(qreg[6], f.x, s0); s1 = fmaf(qreg[7], f.y, s1);
                f = __bfloat1622float2(*(const __nv_bfloat162*)&ku1.x);
                s0 = fmaf(qreg[8], f.x, s0); s1 = fmaf(qreg[9], f.y, s1);
                f = __bfloat1622float2(*(const __nv_bfloat162*)&ku1.y);
                s0 = fmaf(qreg[10], f.x, s0); s1 = fmaf(qreg[11], f.y, s1);
                f = __bfloat1622float2(*(const __nv_bfloat162*)&ku1.z);
                s0 = fmaf(qreg[12], f.x, s0); s1 = fmaf(qreg[13], f.y, s1);
                f = __bfloat1622float2(*(const __nv_bfloat162*)&ku1.w);
                s0 = fmaf(qreg[14], f.x, s0); s1 = fmaf(qreg[15], f.y, s1);
            }
            float s = s0 + s1;
            s += __shfl_xor_sync(qmask, s, 1);
            s += __shfl_xor_sync(qmask, s, 2);
            float newm = fmaxf(m, s);
            float alpha = __expf(m - newm);    // first key: exp(-inf)=0
            float pw = __expf(s - newm);
            l = l * alpha + pw;
            m = newm;
            {
                float2 f;
                f = __bfloat1622float2(*(const __nv_bfloat162*)&vu0.x);
                o[0] = fmaf(o[0], alpha, pw * f.x); o[1] = fmaf(o[1], alpha, pw * f.y);
                f = __bfloat1622float2(*(const __nv_bfloat162*)&vu0.y);
                o[2] = fmaf(o[2], alpha, pw * f.x); o[3] = fmaf(o[3], alpha, pw * f.y);
                f = __bfloat1622float2(*(const __nv_bfloat162*)&vu0.z);
                o[4] = fmaf(o[4], alpha, pw * f.x); o[5] = fmaf(o[5], alpha, pw * f.y);
                f = __bfloat1622float2(*(const __nv_bfloat162*)&vu0.w);
                o[6] = fmaf(o[6], alpha, pw * f.x); o[7] = fmaf(o[7], alpha, pw * f.y);
                f = __bfloat1622float2(*(const __nv_bfloat162*)&vu1.x);
                o[8] = fmaf(o[8], alpha, pw * f.x); o[9] = fmaf(o[9], alpha, pw * f.y);
                f = __bfloat1622float2(*(const __nv_bfloat162*)&vu1.y);
                o[10] = fmaf(o[10], alpha, pw * f.x); o[11] = fmaf(o[11], alpha, pw * f.y);
                f = __bfloat1622float2(*(const __nv_bfloat162*)&vu1.z);
                o[12] = fmaf(o[12], alpha, pw * f.x); o[13] = fmaf(o[13], alpha, pw * f.y);
                f = __bfloat1622float2(*(const __nv_bfloat162*)&vu1.w);
                o[14] = fmaf(o[14], alpha, pw * f.x); o[15] = fmaf(o[15], alpha, pw * f.y);
            }
            p++;
        }
    }

    float invl = 1.0f / l;                 // diagonal => l > 0 always
    float* orow = out + ((size_t)b * NN + row) * DD + h * DK + ql * 16;
    #pragma unroll
    for (int d = 0; d < 16; d += 4) {
        float4 t;
        t.x = o[d] * invl;     t.y = o[d + 1] * invl;
        t.z = o[d + 2] * invl; t.w = o[d + 3] * invl;
        *(float4*)(orow + d) = t;
    }
}

// ---------------- host launcher --------------------------------------------
extern "C" void kernel_launch(void* const* d_in, const int* in_sizes, int n_in,
                              void* d_out, int out_size) {
    const float* x        = (const float*)d_in[0];
    const unsigned char* o2o = (const unsigned char*)d_in[1];
    const int*   positions= (const int*)d_in[2];
    const float* wq = (const float*)d_in[3];  const float* bq = (const float*)d_in[4];
    const float* wk = (const float*)d_in[5];  const float* bk = (const float*)d_in[6];
    const float* wv = (const float*)d_in[7];  const float* bv = (const float*)d_in[8];
    const float* wo = (const float*)d_in[9];  const float* bo = (const float*)d_in[10];
    const float* ln1_g = (const float*)d_in[11]; const float* ln1_b = (const float*)d_in[12];
    const float* ln2_g = (const float*)d_in[13]; const float* ln2_b = (const float*)d_in[14];
    const float* w1 = (const float*)d_in[15]; const float* b1 = (const float*)d_in[16];
    const float* w2 = (const float*)d_in[17]; const float* b2 = (const float*)d_in[18];
    float* out = (float*)d_out;

    float *p_xn, *p_q, *p_att, *p_x2, *p_h, *p_act;
    __nv_bfloat16 *p_kb, *p_vb;
    cudaGetSymbolAddress((void**)&p_xn,  g_xn);
    cudaGetSymbolAddress((void**)&p_q,   g_q);
    cudaGetSymbolAddress((void**)&p_kb,  g_kb);
    cudaGetSymbolAddress((void**)&p_vb,  g_vb);
    cudaGetSymbolAddress((void**)&p_att, g_att);
    cudaGetSymbolAddress((void**)&p_x2,  g_x2);
    cudaGetSymbolAddress((void**)&p_h,   g_h);
    cudaGetSymbolAddress((void**)&p_act, g_act);

    cudaFuncSetAttribute(tgemm_kernel<0,1>, cudaFuncAttributeMaxDynamicSharedMemorySize, GK_SMEM);
    cudaFuncSetAttribute(tgemm_kernel<0,2>, cudaFuncAttributeMaxDynamicSharedMemorySize, GK_SMEM);
    cudaFuncSetAttribute(tgemm_kernel<2,0>, cudaFuncAttributeMaxDynamicSharedMemorySize, GK_SMEM);
    cudaFuncSetAttribute(tgemm_kernel<1,0>, cudaFuncAttributeMaxDynamicSharedMemorySize, GK_SMEM);

    // 0) probes / tables / index lists
    probe_mask_kernel<<<1, 256>>>(o2o);
    rope_init_kernel<<<1, 32>>>();
    build_idx_kernel<<<MROWS / 8, 256>>>(o2o);

    // 1) LN1
    ln_kernel<<<MROWS, 128>>>(x, ln1_g, ln1_b, p_xn);

    // 2) Q/K/V projections -> (B,H,N,DK); Q fp32, K/V bf16
    dim3 gproj(DD / 128, MROWS / 128);
    tgemm_kernel<0,1><<<gproj, 256, GK_SMEM>>>(p_xn, wq, bq, nullptr, p_q, nullptr, MROWS, DD, DD);
    tgemm_kernel<0,2><<<gproj, 256, GK_SMEM>>>(p_xn, wk, bk, nullptr, nullptr, p_kb, MROWS, DD, DD);
    tgemm_kernel<0,2><<<gproj, 256, GK_SMEM>>>(p_xn, wv, bv, nullptr, nullptr, p_vb, MROWS, DD, DD);

    // 3) RoPE on q,k
    rope_kernel<<<(BB * HH * NN * 32) / 256, 256>>>(p_q, p_kb, positions);

    // 4) windowed L1-reuse sparse attention -> (B,N,D)
    dim3 gatt(BB * HH, NN / AW_ROWS);
    attn_win_kernel<<<gatt, 512>>>(p_q, p_kb, p_vb, p_att);

    // 5) output projection + residual
    tgemm_kernel<2,0><<<gproj, 256, GK_SMEM>>>(p_att, wo, bo, x, p_x2, nullptr, MROWS, DD, DD);

    // 6) LN2
    ln_kernel<<<MROWS, 128>>>(p_x2, ln2_g, ln2_b, p_h);

    // 7) FFN up + relu
    dim3 gffn1(FFN / 128, MROWS / 128);
    tgemm_kernel<1,0><<<gffn1, 256, GK_SMEM>>>(p_h, w1, b1, nullptr, p_act, nullptr, MROWS, FFN, DD);

    // 8) FFN down + residual -> out
    tgemm_kernel<2,0><<<gproj, 256, GK_SMEM>>>(p_act, w2, b2, p_x2, out, nullptr, MROWS, DD, FFN);
}